// round 16
// baseline (speedup 1.0000x reference)
#include <cuda_runtime.h>
#include <cstdint>
#include <cstddef>

#define Q      2048
#define NB2    64
#define NSTEP  (Q/NB2)        // 32
#define NCTA   148
#define NTEAM  (2*NCTA)       // 296 global teams; team 0 = potf team
#define LP     68             // smem pitch
#define NTHR   256

// ---------------- scratch (device globals; no allocations allowed) ----------
__device__ float  g_A[Q*Q];                 // working matrix / Cholesky factor
__device__ float  g_Linv[NSTEP*NB2*NB2];    // per-step inverse of diag block
__device__ float  g_w[Q];
__device__ int    g_cnt[Q];
__device__ float  g_v[Q];
__device__ double g_red[4];                 // [0]=m'm [1]=sum r^2 [2]=sum log Lkk
__device__ unsigned g_barCnt;               // grid barrier MONOTONIC arrival counter

extern __shared__ float sh[];

// ---------------- grid barrier: CG-style, thread0-only release/acquire ------
__device__ __forceinline__ void grid_bar(unsigned &target) {
  __syncthreads();
  if (threadIdx.x == 0) {
    target += NCTA;
    asm volatile("red.release.gpu.global.add.u32 [%0], 1;"
                 :: "l"(&g_barCnt) : "memory");
    unsigned cur;
    do {
      asm volatile("ld.acquire.gpu.global.u32 %0, [%1];"
                   : "=r"(cur) : "l"(&g_barCnt) : "memory");
    } while (cur < target);
  }
  __syncthreads();
}

__device__ __forceinline__ void team_bar(int team) {
  asm volatile("bar.sync %0, 128;" :: "r"(team + 4) : "memory");
}
__device__ __forceinline__ void bar4() {           // potf team barrier (team 0)
  asm volatile("bar.sync 4, 128;" ::: "memory");
}

// ---------------- reductions ----------------
__device__ __forceinline__ double block_reduce_1024(double v, double* scratch) {
  #pragma unroll
  for (int o = 16; o; o >>= 1) v += __shfl_down_sync(0xffffffffu, v, o);
  if ((threadIdx.x & 31) == 0) scratch[threadIdx.x >> 5] = v;
  __syncthreads();
  double r = 0.0;
  if (threadIdx.x < 32) {
    r = scratch[threadIdx.x];
    #pragma unroll
    for (int o = 16; o; o >>= 1) r += __shfl_down_sync(0xffffffffu, r, o);
  }
  __syncthreads();
  return r;
}

// ---------------- small kernels ----------------
__global__ void k_reset() {
  int i = blockIdx.x * blockDim.x + threadIdx.x;
  if (i < Q) { g_w[i] = 0.f; g_cnt[i] = 0; }
  if (i < 4) g_red[i] = 0.0;
  if (i == 0) g_barCnt = 0u;
}

__global__ void k_obs(const float* __restrict__ yt, const float* __restrict__ yp,
                      const int* __restrict__ z,
                      const float* __restrict__ pe, const float* __restrict__ pb, int n) {
  int i = blockIdx.x * blockDim.x + threadIdx.x;
  float m = 0.f, r = 0.f;
  if (i < n) {
    r = yt[i] - yp[i];
    float s2 = pe[0] + pb[0];
    float u  = 0.5f * (erff(r / sqrtf(2.f * s2)) + 1.f);
    u = fminf(fmaxf(u, 1e-5f), 1.f - 1e-5f);
    m = erfinvf(2.f * u - 1.f) * 1.41421356237309515f;
    atomicAdd(&g_cnt[z[i]], 1);
    atomicAdd(&g_w[z[i]], m);
  }
  double mm = (double)m * (double)m;
  double rr = (double)r * (double)r;
  #pragma unroll
  for (int o = 16; o; o >>= 1) {
    mm += __shfl_down_sync(0xffffffffu, mm, o);
    rr += __shfl_down_sync(0xffffffffu, rr, o);
  }
  if ((threadIdx.x & 31) == 0) { atomicAdd(&g_red[0], mm); atomicAdd(&g_red[1], rr); }
}

__global__ void k_build(const float* __restrict__ dist, const float* __restrict__ pe,
                        const float* __restrict__ pb, const float* __restrict__ pl) {
  int idx = blockIdx.x * 256 + threadIdx.x;
  int i  = idx >> 9;
  int j4 = idx & 511;
  int j = j4 * 4;
  float inv2l = 0.5f / pl[0];
  int ci = g_cnt[i];
  int4 cj = *(const int4*)(g_cnt + j);
  float sci = sqrtf((float)ci) * pb[0];
  float4 d = *(const float4*)(dist + (size_t)i * Q + j);
  float4 o;
  o.x = sci * sqrtf((float)cj.x) * expf(-d.x * inv2l);
  o.y = sci * sqrtf((float)cj.y) * expf(-d.y * inv2l);
  o.z = sci * sqrtf((float)cj.z) * expf(-d.z * inv2l);
  o.w = sci * sqrtf((float)cj.w) * expf(-d.w * inv2l);
  if (i >= j && i < j + 4) ((float*)&o)[i - j] += pe[0];
  *(float4*)(g_A + (size_t)i * Q + j) = o;
  if (idx < Q) {
    int c = g_cnt[idx];
    g_v[idx] = (c > 0) ? g_w[idx] * rsqrtf((float)c) : 0.f;
  }
}

// ---------------- 32x32 register factor + inverse (one warp) ----------------
__device__ __forceinline__ void fact32(float* ds, float* li, float* lg,
                                       int base, int lane) {
  float a[32];
  #pragma unroll
  for (int j = 0; j < 32; j++) a[j] = ds[(base + lane) * LP + base + j];
  #pragma unroll
  for (int j = 0; j < 32; j++) {
    float dj  = __shfl_sync(0xffffffffu, a[j], j);
    float d   = sqrtf(dj);
    float inv = 1.f / d;
    if (lane == j)     a[j] = d;
    else if (lane > j) a[j] *= inv;
    float lj = a[j];
    #pragma unroll
    for (int k = j + 1; k < 32; k++) {
      float Lkj = __shfl_sync(0xffffffffu, a[j], k);
      if (lane >= k) a[k] -= lj * Lkj;
    }
  }
  #pragma unroll
  for (int j = 0; j < 32; j++)
    if (j <= lane) ds[(base + lane) * LP + base + j] = a[j];
  lg[base + lane] = logf(a[lane]);
  float dinvl = 1.f / a[lane];
  float x[32];
  #pragma unroll
  for (int r = 0; r < 32; r++) x[r] = (r == lane) ? 1.f : 0.f;
  #pragma unroll
  for (int k = 0; k < 32; k++) {
    float dk = __shfl_sync(0xffffffffu, dinvl, k);
    x[k] *= dk;
    float xk = x[k];
    #pragma unroll
    for (int r = k + 1; r < 32; r++) {
      float Lrk = __shfl_sync(0xffffffffu, a[k], r);
      x[r] -= Lrk * xk;
    }
  }
  #pragma unroll
  for (int r = 0; r < 32; r++)
    if (r >= lane) li[(base + r) * LP + base + lane] = x[r];
}

// ---------------- 64x64 potf, run by the potf team (128 threads, bar4) ------
// Loads diag block (k0d), optionally applies ds -= xs*xs^T first, factors,
// writes L (lower) to g_A, Linv to g_Linv[step], logdet to g_red[2].
__device__ void potf_core(float* ds, float* li, float* lg, const float* xs,
                          int k0d, int step, bool presyrk, int wtid) {
  for (int idx = wtid; idx < 64 * 64; idx += 128) {
    int r = idx >> 6, c = idx & 63;
    ds[r * LP + c] = g_A[(size_t)(k0d + r) * Q + k0d + c];
    li[r * LP + c] = 0.f;
  }
  bar4();

  if (presyrk) {
    for (int t = wtid; t < 528; t += 128) {    // lower 2x2 tiles of 64x64
      int di = (int)((sqrtf(8.f * (float)t + 1.f) - 1.f) * 0.5f);
      while ((di + 1) * (di + 2) / 2 <= t) di++;
      while (di * (di + 1) / 2 > t) di--;
      int dj = t - di * (di + 1) / 2;
      int tr = di * 2, tc = dj * 2;
      float a00 = 0.f, a01 = 0.f, a10 = 0.f, a11 = 0.f;
      #pragma unroll 8
      for (int k = 0; k < 64; k++) {
        float x0 = xs[(tr + 0) * LP + k], x1 = xs[(tr + 1) * LP + k];
        float y0 = xs[(tc + 0) * LP + k], y1 = xs[(tc + 1) * LP + k];
        a00 += x0 * y0; a01 += x0 * y1; a10 += x1 * y0; a11 += x1 * y1;
      }
      ds[(tr + 0) * LP + tc + 0] -= a00;
      ds[(tr + 0) * LP + tc + 1] -= a01;
      ds[(tr + 1) * LP + tc + 0] -= a10;
      ds[(tr + 1) * LP + tc + 1] -= a11;
    }
    bar4();
  }

  if (wtid < 32) fact32(ds, li, lg, 0, wtid);
  bar4();

  // X = B * M1^T  (B = ds[32:64, 0:32]); 128 threads, 8 outputs each
  {
    int r = wtid >> 2, c0 = (wtid & 3) * 8;
    float acc[8] = {};
    #pragma unroll
    for (int k = 0; k < 32; k++) {
      float b = ds[(32 + r) * LP + k];
      #pragma unroll
      for (int c = 0; c < 8; c++) acc[c] += b * li[(c0 + c) * LP + k];
    }
    bar4();
    #pragma unroll
    for (int c = 0; c < 8; c++) ds[(32 + r) * LP + c0 + c] = acc[c];
    bar4();
  }

  // S22 -= X*X^T : lower 2x2 tiles (136)
  for (int t = wtid; t < 136; t += 128) {
    int di = 0;
    while ((di + 1) * (di + 2) / 2 <= t) di++;
    int dj = t - di * (di + 1) / 2;
    int tr = 32 + di * 2, tc = 32 + dj * 2;
    float a00 = 0.f, a01 = 0.f, a10 = 0.f, a11 = 0.f;
    #pragma unroll
    for (int k = 0; k < 32; k++) {
      float x0 = ds[(tr + 0) * LP + k], x1 = ds[(tr + 1) * LP + k];
      float y0 = ds[(tc + 0) * LP + k], y1 = ds[(tc + 1) * LP + k];
      a00 += x0 * y0; a01 += x0 * y1; a10 += x1 * y0; a11 += x1 * y1;
    }
    ds[(tr + 0) * LP + tc + 0] -= a00;
    ds[(tr + 0) * LP + tc + 1] -= a01;
    ds[(tr + 1) * LP + tc + 0] -= a10;
    ds[(tr + 1) * LP + tc + 1] -= a11;
  }
  bar4();

  if (wtid < 32) fact32(ds, li, lg, 32, wtid);
  bar4();

  // T = L21 * M1 -> scratch li[0:32, 32:64]
  for (int t = wtid; t < 1024; t += 128) {
    int i = t >> 5, j = t & 31;
    float acc = 0.f;
    #pragma unroll 8
    for (int k = 0; k < 32; k++)
      acc += ds[(32 + i) * LP + k] * li[k * LP + j];
    li[i * LP + 32 + j] = acc;
  }
  bar4();
  // M21 = -M2 * T -> li[32:64, 0:32]
  for (int t = wtid; t < 1024; t += 128) {
    int i = t >> 5, j = t & 31;
    float acc = 0.f;
    #pragma unroll 8
    for (int k = 0; k < 32; k++)
      acc += li[(32 + i) * LP + 32 + k] * li[k * LP + 32 + j];
    li[(32 + i) * LP + j] = -acc;
  }
  bar4();
  for (int t = wtid; t < 1024; t += 128) {
    int i = t >> 5, j = t & 31;
    li[i * LP + 32 + j] = 0.f;
  }
  bar4();

  for (int idx = wtid; idx < 64 * 64; idx += 128) {
    int r = idx >> 6, c = idx & 63;
    if (c <= r) g_A[(size_t)(k0d + r) * Q + k0d + c] = ds[r * LP + c];
    g_Linv[step * 4096 + idx] = li[r * LP + c];
  }
  if (wtid == 0) {
    double acc = 0.0;
    for (int j = 0; j < 64; j++) acc += (double)lg[j];
    atomicAdd(&g_red[2], acc);
  }
}

// ---------------- trsm of one 16-row chunk (one team) -----------------------
__device__ __forceinline__ void trsm_chunk(int k0, int c, float* as, const float* li,
                                           int wtid, int team, float* xs, int xrow0) {
  int r0 = k0 + NB2 + c * 16;
  #pragma unroll
  for (int u = 0; u < 2; u++) {
    int t2 = wtid + u * 128;
    int r = t2 >> 4, c4 = t2 & 15;
    float4 va = *(const float4*)(g_A + (size_t)(r0 + r) * Q + k0 + c4 * 4);
    *(float4*)(as + r * LP + c4 * 4) = va;
  }
  team_bar(team);
  int row = wtid & 15, cg = wtid >> 4;
  float acc[8] = {};
  #pragma unroll
  for (int k4 = 0; k4 < 16; k4++) {
    float4 a4 = *(const float4*)(as + row * LP + k4 * 4);
    #pragma unroll
    for (int cc = 0; cc < 8; cc++) {
      float4 m4 = *(const float4*)(li + (cg * 8 + cc) * LP + k4 * 4);
      acc[cc] += a4.x * m4.x + a4.y * m4.y + a4.z * m4.z + a4.w * m4.w;
    }
  }
  float* dst = g_A + (size_t)(r0 + row) * Q + k0 + cg * 8;
  *(float4*)dst       = make_float4(acc[0], acc[1], acc[2], acc[3]);
  *(float4*)(dst + 4) = make_float4(acc[4], acc[5], acc[6], acc[7]);
  if (xs) {
    float* xd = xs + (size_t)(xrow0 + row) * LP + cg * 8;
    *(float4*)xd       = make_float4(acc[0], acc[1], acc[2], acc[3]);
    *(float4*)(xd + 4) = make_float4(acc[4], acc[5], acc[6], acc[7]);
  }
  team_bar(team);
}

// ---------------- 64x64 syrk GEMM core (K=64), 128-thread team --------------
__device__ __forceinline__ void gemm64_k64(const float* __restrict__ aRow,
                                           const float* __restrict__ bRow,
                                           float* as, float* bs, int wtid, int team,
                                           float acc[8][4]) {
  int tx = wtid & 15, ty = wtid >> 4;
  for (int kk = 0; kk < 64; kk += 16) {
    #pragma unroll
    for (int i2 = 0; i2 < 2; i2++) {
      int li2 = wtid + i2 * 128;
      int r = li2 >> 2, c4 = li2 & 3;
      float4 va = *(const float4*)(aRow + (size_t)r * Q + kk + c4 * 4);
      float4 vb = *(const float4*)(bRow + (size_t)r * Q + kk + c4 * 4);
      as[(c4 * 4 + 0) * LP + r] = va.x; as[(c4 * 4 + 1) * LP + r] = va.y;
      as[(c4 * 4 + 2) * LP + r] = va.z; as[(c4 * 4 + 3) * LP + r] = va.w;
      bs[(c4 * 4 + 0) * LP + r] = vb.x; bs[(c4 * 4 + 1) * LP + r] = vb.y;
      bs[(c4 * 4 + 2) * LP + r] = vb.z; bs[(c4 * 4 + 3) * LP + r] = vb.w;
    }
    team_bar(team);
    #pragma unroll
    for (int k = 0; k < 16; k++) {
      float4 A0 = *(const float4*)&as[k * LP + ty * 8];
      float4 A1 = *(const float4*)&as[k * LP + ty * 8 + 4];
      float4 B0 = *(const float4*)&bs[k * LP + tx * 4];
      float ar[8] = {A0.x, A0.y, A0.z, A0.w, A1.x, A1.y, A1.z, A1.w};
      float br[4] = {B0.x, B0.y, B0.z, B0.w};
      #pragma unroll
      for (int i = 0; i < 8; i++)
        #pragma unroll
        for (int j = 0; j < 4; j++)
          acc[i][j] += ar[i] * br[j];
    }
    team_bar(team);
  }
}

// ---------------- persistent pipelined Cholesky ------------------------------
__global__ void __launch_bounds__(NTHR, 1) k_chol() {
  int tid  = threadIdx.x;
  int team = tid >> 7, wtid = tid & 127;
  int gt   = blockIdx.x * 2 + team;        // global team id; 0 = potf team
  float* ds = sh;                          // 64*LP
  float* li = ds + 64 * LP;                // 64*LP  (Linv(s) copy / potf scratch)
  float* xs = li + 64 * LP;                // 64*LP  (CTA0's X of block row s+1)
  float* lg = xs + 64 * LP;                // 64
  float* as = lg + 64 + team * (2 * 16 * LP);
  float* bs = as + 16 * LP;
  unsigned bt = 0;

  // prologue: potf(0) by team 0 only
  if (gt == 0) potf_core(ds, li, lg, xs, 0, 0, false, wtid);
  grid_bar(bt);

  #pragma unroll 1
  for (int s = 0; s < NSTEP - 1; s++) {
    int k0 = s * NB2;
    int nrows = Q - k0 - NB2;              // >= 64
    int nch = nrows >> 4;

    // ---- phase 1: load Linv(s); trsm column s ----
    for (int idx = tid; idx < 4096; idx += NTHR)
      li[(idx >> 6) * LP + (idx & 63)] = g_Linv[s * 4096 + idx];
    __syncthreads();
    if (gt == 0) {
      #pragma unroll
      for (int c = 0; c < 4; c++)
        trsm_chunk(k0, c, as, li, wtid, team, xs, c * 16);   // block row s+1
    } else {
      for (int c = 4 + (gt - 1); c < nch; c += NTEAM - 1)
        trsm_chunk(k0, c, as, li, wtid, team, (float*)0, 0);
    }
    grid_bar(bt);

    // ---- phase 2: team0 -> fused diag-syrk + potf(s+1); others -> syrk sweep
    int nT = nrows >> 6;
    int njS = nT * (nT + 1) / 2;
    int t0 = k0 + NB2;
    if (gt == 0) {
      potf_core(ds, li, lg, xs, t0, s + 1, true, wtid);
    } else {
      for (int j = 1 + (gt - 1); j < njS; j += NTEAM - 1) {
        int ti = (int)((sqrtf(8.f * (float)j + 1.f) - 1.f) * 0.5f);
        while ((ti + 1) * (ti + 2) / 2 <= j) ti++;
        while (ti * (ti + 1) / 2 > j) ti--;
        int tj = j - ti * (ti + 1) / 2;
        const float* aRow = g_A + (size_t)(t0 + ti * 64) * Q + k0;
        const float* bRow = g_A + (size_t)(t0 + tj * 64) * Q + k0;
        float acc[8][4] = {};
        gemm64_k64(aRow, bRow, as, bs, wtid, team, acc);
        int tx = wtid & 15, ty = wtid >> 4;
        #pragma unroll
        for (int i = 0; i < 8; i++) {
          float* cp = g_A + (size_t)(t0 + ti * 64 + ty * 8 + i) * Q + t0 + tj * 64 + tx * 4;
          float4 v = *(float4*)cp;
          v.x -= acc[i][0]; v.y -= acc[i][1]; v.z -= acc[i][2]; v.w -= acc[i][3];
          *(float4*)cp = v;
        }
      }
    }
    grid_bar(bt);
  }
}

// ---------------- forward solve + final assembly (single CTA, 1024 thr) ----
__global__ void k_solve(float* __restrict__ out, const float* __restrict__ pe,
                        const float* __restrict__ pb, int n) {
  float* vbuf = sh;         // Q
  float* ybuf = sh + Q;     // Q
  __shared__ double dred[32];
  int tid = threadIdx.x;

  for (int i = tid; i < Q; i += 1024) vbuf[i] = g_v[i];
  __syncthreads();

  double pv = 0.0;
  for (int i = tid; i < Q; i += 1024) { double t = vbuf[i]; pv += t * t; }
  double vtv = block_reduce_1024(pv, dred);

  int row16 = tid >> 4, l16 = tid & 15;
  int w = tid >> 5, lane = tid & 31;
  int rsub = lane >> 3, jj = lane & 7;

  for (int b = 0; b < NSTEP; b++) {
    int c0 = b * NB2;
    const float* Li = g_Linv + b * 4096;
    float4 a = *(const float4*)(Li + row16 * 64 + l16 * 4);
    float4 v = *(const float4*)(&vbuf[c0 + l16 * 4]);
    float acc = a.x * v.x + a.y * v.y + a.z * v.z + a.w * v.w;
    #pragma unroll
    for (int o = 8; o; o >>= 1) acc += __shfl_down_sync(0xffffffffu, acc, o, 16);
    if (l16 == 0) ybuf[c0 + row16] = acc;
    __syncthreads();

    const float4* Yb = (const float4*)&ybuf[c0];
    float4 yr0 = Yb[jj], yr1 = Yb[jj + 8];
    #pragma unroll 2
    for (int r4 = c0 + NB2 + w * 4; r4 < Q; r4 += 128) {
      int r = r4 + rsub;
      const float4* Ar = (const float4*)&g_A[(size_t)r * Q + c0];
      float4 a0 = Ar[jj], a1 = Ar[jj + 8];
      float s = a0.x * yr0.x + a0.y * yr0.y + a0.z * yr0.z + a0.w * yr0.w
              + a1.x * yr1.x + a1.y * yr1.y + a1.z * yr1.z + a1.w * yr1.w;
      s += __shfl_down_sync(0xffffffffu, s, 4, 8);
      s += __shfl_down_sync(0xffffffffu, s, 2, 8);
      s += __shfl_down_sync(0xffffffffu, s, 1, 8);
      if (jj == 0) vbuf[r] -= s;
    }
    __syncthreads();
  }

  double py = 0.0;
  for (int i = tid; i < Q; i += 1024) { double t = ybuf[i]; py += t * t; }
  double yty = block_reduce_1024(py, dred);

  if (tid == 0) {
    double mtm = g_red[0], sumR2 = g_red[1], logdetA = 2.0 * g_red[2];
    double s2e = (double)pe[0], s2b = (double)pb[0], s2 = s2e + s2b;
    double dn = (double)n;
    double logdetR = (dn - (double)Q) * log(s2e) + logdetA - dn * log(s2);
    double mVm = (mtm - vtv + s2e * yty) / s2e;
    double slp = -0.5 * dn * log(6.283185307179586 * s2) - sumR2 / (2.0 * s2);
    double total = 0.5 * logdetR + 0.5 * s2 * mVm - 0.5 * mtm + 0.5 * slp;
    out[0] = (float)total;
  }
}

// ---------------- host ----------------
extern "C" void kernel_launch(void* const* d_in, const int* in_sizes, int n_in,
                              void* d_out, int out_size) {
  const float* y_true = (const float*)d_in[0];
  const float* y_pred = (const float*)d_in[1];
  const int*   Z_idx  = (const int*)  d_in[2];
  const float* dist   = (const float*)d_in[3];
  const float* s2e    = (const float*)d_in[4];
  const float* s2b    = (const float*)d_in[5];
  const float* ell    = (const float*)d_in[6];
  int n = in_sizes[0];

  // smem: ds+li+xs (3*64*LP) + lg(64) + 2 teams * (as+bs = 2*16*LP)
  size_t chol_smem  = (size_t)(3 * 64 * LP + 64 + 2 * 2 * 16 * LP) * sizeof(float); // ~70 KB
  size_t solve_smem = (size_t)(2 * Q) * sizeof(float);
  cudaFuncSetAttribute(k_chol,  cudaFuncAttributeMaxDynamicSharedMemorySize, (int)chol_smem);
  cudaFuncSetAttribute(k_solve, cudaFuncAttributeMaxDynamicSharedMemorySize, (int)solve_smem);

  k_reset<<<(Q + 255) / 256, 256>>>();                                   // launch 0
  k_obs<<<(n + 255) / 256, 256>>>(y_true, y_pred, Z_idx, s2e, s2b, n);   // launch 1
  k_build<<<(Q * Q / 4) / 256, 256>>>(dist, s2e, s2b, ell);              // launch 2
  k_chol<<<NCTA, NTHR, chol_smem>>>();                                   // launch 3 (ncu slot)
  k_solve<<<1, 1024, solve_smem>>>((float*)d_out, s2e, s2b, n);          // launch 4
}

// round 17
// speedup vs baseline: 1.0193x; 1.0193x over previous
#include <cuda_runtime.h>
#include <cstdint>
#include <cstddef>

#define Q      2048
#define NBP    128            // panel width
#define NSTEPP 16             // panels
#define NB2    64
#define NSTEP  32             // 64-blocks (for solve/Linv layout)
#define NCTA   148
#define NTHR   256
#define SP     129            // potf smem pitch (conflict-free scalar columns)

// ---------------- scratch (device globals) ----------------------------------
__device__ float  g_A[Q*Q];
__device__ float  g_Linv[NSTEP*NB2*NB2];    // 64x64 diag-block inverses
__device__ float  g_w[Q];
__device__ int    g_cnt[Q];
__device__ float  g_v[Q];
__device__ double g_red[4];
__device__ unsigned g_barCnt;

extern __shared__ float sh[];

// ---------------- grid barrier (CG-style, thread0 release/acquire) ----------
__device__ __forceinline__ void grid_bar(unsigned &target) {
  __syncthreads();
  if (threadIdx.x == 0) {
    target += NCTA;
    asm volatile("red.release.gpu.global.add.u32 [%0], 1;"
                 :: "l"(&g_barCnt) : "memory");
    unsigned cur;
    do {
      asm volatile("ld.acquire.gpu.global.u32 %0, [%1];"
                   : "=r"(cur) : "l"(&g_barCnt) : "memory");
    } while (cur < target);
  }
  __syncthreads();
}

__device__ __forceinline__ void team_bar(int team) {
  asm volatile("bar.sync %0, 128;" :: "r"(team + 4) : "memory");
}

__device__ __forceinline__ double block_reduce_1024(double v, double* scratch) {
  #pragma unroll
  for (int o = 16; o; o >>= 1) v += __shfl_down_sync(0xffffffffu, v, o);
  if ((threadIdx.x & 31) == 0) scratch[threadIdx.x >> 5] = v;
  __syncthreads();
  double r = 0.0;
  if (threadIdx.x < 32) {
    r = scratch[threadIdx.x];
    #pragma unroll
    for (int o = 16; o; o >>= 1) r += __shfl_down_sync(0xffffffffu, r, o);
  }
  __syncthreads();
  return r;
}

// ---------------- small kernels ----------------
__global__ void k_reset() {
  int i = blockIdx.x * blockDim.x + threadIdx.x;
  if (i < Q) { g_w[i] = 0.f; g_cnt[i] = 0; }
  if (i < 4) g_red[i] = 0.0;
  if (i == 0) g_barCnt = 0u;
}

__global__ void k_obs(const float* __restrict__ yt, const float* __restrict__ yp,
                      const int* __restrict__ z,
                      const float* __restrict__ pe, const float* __restrict__ pb, int n) {
  int i = blockIdx.x * blockDim.x + threadIdx.x;
  float m = 0.f, r = 0.f;
  if (i < n) {
    r = yt[i] - yp[i];
    float s2 = pe[0] + pb[0];
    float u  = 0.5f * (erff(r / sqrtf(2.f * s2)) + 1.f);
    u = fminf(fmaxf(u, 1e-5f), 1.f - 1e-5f);
    m = erfinvf(2.f * u - 1.f) * 1.41421356237309515f;
    atomicAdd(&g_cnt[z[i]], 1);
    atomicAdd(&g_w[z[i]], m);
  }
  double mm = (double)m * (double)m;
  double rr = (double)r * (double)r;
  #pragma unroll
  for (int o = 16; o; o >>= 1) {
    mm += __shfl_down_sync(0xffffffffu, mm, o);
    rr += __shfl_down_sync(0xffffffffu, rr, o);
  }
  if ((threadIdx.x & 31) == 0) { atomicAdd(&g_red[0], mm); atomicAdd(&g_red[1], rr); }
}

__global__ void k_build(const float* __restrict__ dist, const float* __restrict__ pe,
                        const float* __restrict__ pb, const float* __restrict__ pl) {
  int idx = blockIdx.x * 256 + threadIdx.x;
  int i  = idx >> 9;
  int j4 = idx & 511;
  int j = j4 * 4;
  float inv2l = 0.5f / pl[0];
  int ci = g_cnt[i];
  int4 cj = *(const int4*)(g_cnt + j);
  float sci = sqrtf((float)ci) * pb[0];
  float4 d = *(const float4*)(dist + (size_t)i * Q + j);
  float4 o;
  o.x = sci * sqrtf((float)cj.x) * expf(-d.x * inv2l);
  o.y = sci * sqrtf((float)cj.y) * expf(-d.y * inv2l);
  o.z = sci * sqrtf((float)cj.z) * expf(-d.z * inv2l);
  o.w = sci * sqrtf((float)cj.w) * expf(-d.w * inv2l);
  if (i >= j && i < j + 4) ((float*)&o)[i - j] += pe[0];
  *(float4*)(g_A + (size_t)i * Q + j) = o;
  if (idx < Q) {
    int c = g_cnt[idx];
    g_v[idx] = (c > 0) ? g_w[idx] * rsqrtf((float)c) : 0.f;
  }
}

// ---------------- 128x128 replicated potf (R7 algorithm, 256 threads) -------
// s: pitch SP working block; li: pitch SP, becomes Linv128 (lower, upper zero)
__device__ void potf128(float* s, float* li, float* lg, int k0, int tid) {
  int lane = tid & 31;
  for (int idx = tid; idx < 128 * 128; idx += NTHR) {
    int r = idx >> 7, c = idx & 127;
    s[r * SP + c]  = g_A[(size_t)(k0 + r) * Q + k0 + c];
    li[r * SP + c] = 0.f;
  }
  __syncthreads();

  #pragma unroll 1
  for (int p = 0; p < 4; p++) {
    int pc = p * 32;
    int nrows = 96 - pc;

    if (tid < 32) {
      // (a) factor 32x32 diag sub-block in registers
      float a[32];
      #pragma unroll
      for (int j = 0; j < 32; j++) a[j] = s[(pc + lane) * SP + pc + j];
      #pragma unroll
      for (int j = 0; j < 32; j++) {
        float dj  = __shfl_sync(0xffffffffu, a[j], j);
        float d   = sqrtf(dj);
        float inv = 1.f / d;
        if (lane == j)     a[j] = d;
        else if (lane > j) a[j] *= inv;
        float lj = a[j];
        #pragma unroll
        for (int k = j + 1; k < 32; k++) {
          float Lkj = __shfl_sync(0xffffffffu, a[j], k);
          if (lane >= k) a[k] -= lj * Lkj;
        }
      }
      #pragma unroll
      for (int j = 0; j < 32; j++)
        if (j <= lane) s[(pc + lane) * SP + pc + j] = a[j];
      lg[pc + lane] = logf(a[lane]);
      // (b) invert 32x32 in registers (lane = column)
      float dinvl = 1.f / a[lane];
      float x[32];
      #pragma unroll
      for (int r = 0; r < 32; r++) x[r] = (r == lane) ? 1.f : 0.f;
      #pragma unroll
      for (int k = 0; k < 32; k++) {
        float dk = __shfl_sync(0xffffffffu, dinvl, k);
        x[k] *= dk;
        float xk = x[k];
        #pragma unroll
        for (int r = k + 1; r < 32; r++) {
          float Lrk = __shfl_sync(0xffffffffu, a[k], r);
          x[r] -= Lrk * xk;
        }
      }
      #pragma unroll
      for (int r = 0; r < 32; r++)
        if (r >= lane) li[(pc + r) * SP + pc + lane] = x[r];
    }
    __syncthreads();

    if (nrows > 0) {
      // (c) rows below: X = B * M^T, 4x4 register tiles (ntr*8 <= 192 < 256)
      int ntr = nrows >> 2;
      float acc[4][4] = {};
      int ti = tid >> 3, tj = tid & 7;
      bool active = (tid < ntr * 8);
      if (active) {
        int r0 = pc + 32 + ti * 4;
        int m0 = pc + tj * 4;
        #pragma unroll
        for (int k = 0; k < 32; k++) {
          float b0 = s[(r0 + 0) * SP + pc + k], b1 = s[(r0 + 1) * SP + pc + k];
          float b2 = s[(r0 + 2) * SP + pc + k], b3 = s[(r0 + 3) * SP + pc + k];
          float m0v = li[(m0 + 0) * SP + pc + k], m1v = li[(m0 + 1) * SP + pc + k];
          float m2v = li[(m0 + 2) * SP + pc + k], m3v = li[(m0 + 3) * SP + pc + k];
          acc[0][0] += b0 * m0v; acc[0][1] += b0 * m1v; acc[0][2] += b0 * m2v; acc[0][3] += b0 * m3v;
          acc[1][0] += b1 * m0v; acc[1][1] += b1 * m1v; acc[1][2] += b1 * m2v; acc[1][3] += b1 * m3v;
          acc[2][0] += b2 * m0v; acc[2][1] += b2 * m1v; acc[2][2] += b2 * m2v; acc[2][3] += b2 * m3v;
          acc[3][0] += b3 * m0v; acc[3][1] += b3 * m1v; acc[3][2] += b3 * m2v; acc[3][3] += b3 * m3v;
        }
      }
      __syncthreads();
      if (active) {
        int r0 = pc + 32 + ti * 4;
        int c0 = pc + tj * 4;
        #pragma unroll
        for (int i = 0; i < 4; i++)
          #pragma unroll
          for (int j = 0; j < 4; j++)
            s[(r0 + i) * SP + c0 + j] = acc[i][j];
      }
      __syncthreads();

      // (d) trailing update within panel, LOWER 4x4 tiles
      int ntile = ntr * (ntr + 1) / 2;    // <= 300
      for (int t2 = tid; t2 < ntile; t2 += NTHR) {
        int di = (int)((sqrtf(8.f * (float)t2 + 1.f) - 1.f) * 0.5f);
        while ((di + 1) * (di + 2) / 2 <= t2) di++;
        while (di * (di + 1) / 2 > t2) di--;
        int dj = t2 - di * (di + 1) / 2;
        int tr = pc + 32 + di * 4, tc = pc + 32 + dj * 4;
        float a2[4][4] = {};
        #pragma unroll
        for (int k = 0; k < 32; k++) {
          float a0 = s[(tr + 0) * SP + pc + k], a1 = s[(tr + 1) * SP + pc + k];
          float aa = s[(tr + 2) * SP + pc + k], a3 = s[(tr + 3) * SP + pc + k];
          float b0 = s[(tc + 0) * SP + pc + k], b1 = s[(tc + 1) * SP + pc + k];
          float b2 = s[(tc + 2) * SP + pc + k], b3 = s[(tc + 3) * SP + pc + k];
          a2[0][0] += a0 * b0; a2[0][1] += a0 * b1; a2[0][2] += a0 * b2; a2[0][3] += a0 * b3;
          a2[1][0] += a1 * b0; a2[1][1] += a1 * b1; a2[1][2] += a1 * b2; a2[1][3] += a1 * b3;
          a2[2][0] += aa * b0; a2[2][1] += aa * b1; a2[2][2] += aa * b2; a2[2][3] += aa * b3;
          a2[3][0] += a3 * b0; a2[3][1] += a3 * b1; a2[3][2] += a3 * b2; a2[3][3] += a3 * b3;
        }
        #pragma unroll
        for (int i = 0; i < 4; i++)
          #pragma unroll
          for (int j = 0; j < 4; j++)
            s[(tr + i) * SP + tc + j] -= a2[i][j];
      }
      __syncthreads();
    }
  }

  // assemble off-diagonal blocks of inv(L11), staged by block-diag distance
  {
    const int s_begin[4] = {0, 3, 5, 6};
    const int prs[6] = {1, 2, 3, 2, 3, 3};
    const int pcs[6] = {0, 1, 2, 0, 1, 0};
    for (int st = 0; st < 3; st++) {
      int e0 = s_begin[st], e1 = s_begin[st + 1];
      int np = e1 - e0;
      for (int t = tid; t < np * 1024; t += NTHR) {
        int e = e0 + (t >> 10);
        int cell = t & 1023;
        int i = cell >> 5, j = cell & 31;
        int r = prs[e], c = pcs[e];
        float acc = 0.f;
        for (int kb2 = c; kb2 < r; kb2++)
          #pragma unroll 8
          for (int k = 0; k < 32; k++)
            acc += s[(32 * r + i) * SP + 32 * kb2 + k] * li[(32 * kb2 + k) * SP + 32 * c + j];
        li[(32 * c + i) * SP + 32 * r + j] = acc;
      }
      __syncthreads();
      for (int t = tid; t < np * 1024; t += NTHR) {
        int e = e0 + (t >> 10);
        int cell = t & 1023;
        int i = cell >> 5, j = cell & 31;
        int r = prs[e], c = pcs[e];
        float acc = 0.f;
        #pragma unroll 8
        for (int k = 0; k < 32; k++)
          acc += li[(32 * r + i) * SP + 32 * r + k] * li[(32 * c + k) * SP + 32 * r + j];
        li[(32 * r + i) * SP + 32 * c + j] = -acc;
      }
      __syncthreads();
    }
    for (int idx = tid; idx < 128 * 128; idx += NTHR) {
      int r = idx >> 7, c = idx & 127;
      if (c > r) li[r * SP + c] = 0.f;
    }
    __syncthreads();
  }
}

// ---------------- trsm of one 16x128 chunk (one team) ------------------------
// X = A_chunk(16x128) * Linv128^T ; linv: pitch 128 (float4-aligned)
__device__ __forceinline__ void trsm_chunk128(int k0, int c, float* buf,
                                              const float* linv, int wtid, int team) {
  int r0 = k0 + NBP + c * 16;
  #pragma unroll
  for (int u = 0; u < 4; u++) {
    int t2 = wtid + u * 128;        // 512 float4 jobs
    int r = t2 >> 5, c4 = t2 & 31;
    float4 va = *(const float4*)(g_A + (size_t)(r0 + r) * Q + k0 + c4 * 4);
    *(float4*)(buf + r * 132 + c4 * 4) = va;
  }
  team_bar(team);
  int row = wtid & 15, cg = wtid >> 4;   // 8 groups x 16 cols
  float acc[16] = {};
  #pragma unroll 4
  for (int k4 = 0; k4 < 32; k4++) {
    float4 a4 = *(const float4*)(buf + row * 132 + k4 * 4);
    #pragma unroll
    for (int cc = 0; cc < 16; cc++) {
      float4 m4 = *(const float4*)(linv + (cg * 16 + cc) * 128 + k4 * 4);
      acc[cc] += a4.x * m4.x + a4.y * m4.y + a4.z * m4.z + a4.w * m4.w;
    }
  }
  float* dst = g_A + (size_t)(r0 + row) * Q + k0 + cg * 16;
  *(float4*)(dst)      = make_float4(acc[0],  acc[1],  acc[2],  acc[3]);
  *(float4*)(dst + 4)  = make_float4(acc[4],  acc[5],  acc[6],  acc[7]);
  *(float4*)(dst + 8)  = make_float4(acc[8],  acc[9],  acc[10], acc[11]);
  *(float4*)(dst + 12) = make_float4(acc[12], acc[13], acc[14], acc[15]);
  team_bar(team);
}

// ---------------- 64x64 syrk GEMM core (K=128), 128-thread team --------------
__device__ __forceinline__ void gemm64_k128(const float* __restrict__ aRow,
                                            const float* __restrict__ bRow,
                                            float* as, float* bs, int wtid, int team,
                                            float acc[8][4]) {
  int tx = wtid & 15, ty = wtid >> 4;
  for (int kk = 0; kk < 128; kk += 16) {
    #pragma unroll
    for (int i2 = 0; i2 < 2; i2++) {
      int li2 = wtid + i2 * 128;
      int r = li2 >> 2, c4 = li2 & 3;
      float4 va = *(const float4*)(aRow + (size_t)r * Q + kk + c4 * 4);
      float4 vb = *(const float4*)(bRow + (size_t)r * Q + kk + c4 * 4);
      as[(c4 * 4 + 0) * 68 + r] = va.x; as[(c4 * 4 + 1) * 68 + r] = va.y;
      as[(c4 * 4 + 2) * 68 + r] = va.z; as[(c4 * 4 + 3) * 68 + r] = va.w;
      bs[(c4 * 4 + 0) * 68 + r] = vb.x; bs[(c4 * 4 + 1) * 68 + r] = vb.y;
      bs[(c4 * 4 + 2) * 68 + r] = vb.z; bs[(c4 * 4 + 3) * 68 + r] = vb.w;
    }
    team_bar(team);
    #pragma unroll
    for (int k = 0; k < 16; k++) {
      float4 A0 = *(const float4*)&as[k * 68 + ty * 8];
      float4 A1 = *(const float4*)&as[k * 68 + ty * 8 + 4];
      float4 B0 = *(const float4*)&bs[k * 68 + tx * 4];
      float ar[8] = {A0.x, A0.y, A0.z, A0.w, A1.x, A1.y, A1.z, A1.w};
      float br[4] = {B0.x, B0.y, B0.z, B0.w};
      #pragma unroll
      for (int i = 0; i < 8; i++)
        #pragma unroll
        for (int j = 0; j < 4; j++)
          acc[i][j] += ar[i] * br[j];
    }
    team_bar(team);
  }
}

// ---------------- persistent Cholesky: 16 panel steps ------------------------
__global__ void __launch_bounds__(NTHR, 1) k_chol() {
  int tid  = threadIdx.x;
  int team = tid >> 7, wtid = tid & 127;
  float* ds = sh;                         // 128*SP   (potf L, then Linv repack)
  float* li = ds + 128 * SP;              // 128*SP   (Linv128)
  float* lg = li + 128 * SP;              // 128
  float* tb = lg + 128 + team * 2176;     // per-team buffer (2176 floats)
  unsigned bt = 0;

  #pragma unroll 1
  for (int sp2 = 0; sp2 < NSTEPP; sp2++) {
    int k0 = sp2 * NBP;
    potf128(ds, li, lg, k0, tid);

    // CTA0 persists L (lower) and the two 64x64 Linv diag blocks + logdet
    if (blockIdx.x == 0) {
      for (int idx = tid; idx < 128 * 128; idx += NTHR) {
        int r = idx >> 7, c = idx & 127;
        if (c <= r) g_A[(size_t)(k0 + r) * Q + k0 + c] = ds[r * SP + c];
      }
      for (int idx = tid; idx < 4096; idx += NTHR) {
        int r = idx >> 6, c = idx & 63;
        g_Linv[(2 * sp2) * 4096 + idx]     = li[r * SP + c];
        g_Linv[(2 * sp2 + 1) * 4096 + idx] = li[(64 + r) * SP + 64 + c];
      }
      if (tid == 0) {
        double acc = 0.0;
        for (int j = 0; j < 128; j++) acc += (double)lg[j];
        atomicAdd(&g_red[2], acc);
      }
    }
    __syncthreads();
    // repack Linv into ds with pitch 128 (float4-aligned for trsm)
    for (int idx = tid; idx < 128 * 128; idx += NTHR)
      ds[(idx >> 7) * 128 + (idx & 127)] = li[(idx >> 7) * SP + (idx & 127)];
    __syncthreads();

    int nrows = Q - k0 - NBP;
    if (nrows > 0) {
      // ---- trsm: 16-row chunks ----
      int nch = nrows >> 4;
      for (int c = blockIdx.x * 2 + team; c < nch; c += NCTA * 2)
        trsm_chunk128(k0, c, tb, ds, wtid, team);
      grid_bar(bt);

      // ---- syrk: lower 64-tiles, K=128 ----
      int nT = nrows >> 6;
      int njS = nT * (nT + 1) / 2;
      int t0 = k0 + NBP;
      float* as = tb;
      float* bs = tb + 16 * 68;
      for (int j = blockIdx.x * 2 + team; j < njS; j += NCTA * 2) {
        int ti = (int)((sqrtf(8.f * (float)j + 1.f) - 1.f) * 0.5f);
        while ((ti + 1) * (ti + 2) / 2 <= j) ti++;
        while (ti * (ti + 1) / 2 > j) ti--;
        int tj = j - ti * (ti + 1) / 2;
        const float* aRow = g_A + (size_t)(t0 + ti * 64) * Q + k0;
        const float* bRow = g_A + (size_t)(t0 + tj * 64) * Q + k0;
        float acc[8][4] = {};
        gemm64_k128(aRow, bRow, as, bs, wtid, team, acc);
        int tx = wtid & 15, ty = wtid >> 4;
        #pragma unroll
        for (int i = 0; i < 8; i++) {
          float* cp = g_A + (size_t)(t0 + ti * 64 + ty * 8 + i) * Q + t0 + tj * 64 + tx * 4;
          float4 v = *(float4*)cp;
          v.x -= acc[i][0]; v.y -= acc[i][1]; v.z -= acc[i][2]; v.w -= acc[i][3];
          *(float4*)cp = v;
        }
      }
      grid_bar(bt);
    }
  }
}

// ---------------- forward solve + final assembly (single CTA, 1024 thr) ----
__global__ void k_solve(float* __restrict__ out, const float* __restrict__ pe,
                        const float* __restrict__ pb, int n) {
  float* vbuf = sh;
  float* ybuf = sh + Q;
  __shared__ double dred[32];
  int tid = threadIdx.x;

  for (int i = tid; i < Q; i += 1024) vbuf[i] = g_v[i];
  __syncthreads();

  double pv = 0.0;
  for (int i = tid; i < Q; i += 1024) { double t = vbuf[i]; pv += t * t; }
  double vtv = block_reduce_1024(pv, dred);

  int row16 = tid >> 4, l16 = tid & 15;
  int w = tid >> 5, lane = tid & 31;
  int rsub = lane >> 3, jj = lane & 7;

  for (int b = 0; b < NSTEP; b++) {
    int c0 = b * NB2;
    const float* Li = g_Linv + b * 4096;
    float4 a = *(const float4*)(Li + row16 * 64 + l16 * 4);
    float4 v = *(const float4*)(&vbuf[c0 + l16 * 4]);
    float acc = a.x * v.x + a.y * v.y + a.z * v.z + a.w * v.w;
    #pragma unroll
    for (int o = 8; o; o >>= 1) acc += __shfl_down_sync(0xffffffffu, acc, o, 16);
    if (l16 == 0) ybuf[c0 + row16] = acc;
    __syncthreads();

    const float4* Yb = (const float4*)&ybuf[c0];
    float4 yr0 = Yb[jj], yr1 = Yb[jj + 8];
    #pragma unroll 2
    for (int r4 = c0 + NB2 + w * 4; r4 < Q; r4 += 128) {
      int r = r4 + rsub;
      const float4* Ar = (const float4*)&g_A[(size_t)r * Q + c0];
      float4 a0 = Ar[jj], a1 = Ar[jj + 8];
      float s = a0.x * yr0.x + a0.y * yr0.y + a0.z * yr0.z + a0.w * yr0.w
              + a1.x * yr1.x + a1.y * yr1.y + a1.z * yr1.z + a1.w * yr1.w;
      s += __shfl_down_sync(0xffffffffu, s, 4, 8);
      s += __shfl_down_sync(0xffffffffu, s, 2, 8);
      s += __shfl_down_sync(0xffffffffu, s, 1, 8);
      if (jj == 0) vbuf[r] -= s;
    }
    __syncthreads();
  }

  double py = 0.0;
  for (int i = tid; i < Q; i += 1024) { double t = ybuf[i]; py += t * t; }
  double yty = block_reduce_1024(py, dred);

  if (tid == 0) {
    double mtm = g_red[0], sumR2 = g_red[1], logdetA = 2.0 * g_red[2];
    double s2e = (double)pe[0], s2b = (double)pb[0], s2 = s2e + s2b;
    double dn = (double)n;
    double logdetR = (dn - (double)Q) * log(s2e) + logdetA - dn * log(s2);
    double mVm = (mtm - vtv + s2e * yty) / s2e;
    double slp = -0.5 * dn * log(6.283185307179586 * s2) - sumR2 / (2.0 * s2);
    double total = 0.5 * logdetR + 0.5 * s2 * mVm - 0.5 * mtm + 0.5 * slp;
    out[0] = (float)total;
  }
}

// ---------------- host ----------------
extern "C" void kernel_launch(void* const* d_in, const int* in_sizes, int n_in,
                              void* d_out, int out_size) {
  const float* y_true = (const float*)d_in[0];
  const float* y_pred = (const float*)d_in[1];
  const int*   Z_idx  = (const int*)  d_in[2];
  const float* dist   = (const float*)d_in[3];
  const float* s2e    = (const float*)d_in[4];
  const float* s2b    = (const float*)d_in[5];
  const float* ell    = (const float*)d_in[6];
  int n = in_sizes[0];

  // smem: ds(128*129) + li(128*129) + lg(128) + 2 teams * 2176
  size_t chol_smem  = (size_t)(2 * 128 * SP + 128 + 2 * 2176) * sizeof(float); // ~149.5 KB
  size_t solve_smem = (size_t)(2 * Q) * sizeof(float);
  cudaFuncSetAttribute(k_chol,  cudaFuncAttributeMaxDynamicSharedMemorySize, (int)chol_smem);
  cudaFuncSetAttribute(k_solve, cudaFuncAttributeMaxDynamicSharedMemorySize, (int)solve_smem);

  k_reset<<<(Q + 255) / 256, 256>>>();                                   // launch 0
  k_obs<<<(n + 255) / 256, 256>>>(y_true, y_pred, Z_idx, s2e, s2b, n);   // launch 1
  k_build<<<(Q * Q / 4) / 256, 256>>>(dist, s2e, s2b, ell);              // launch 2
  k_chol<<<NCTA, NTHR, chol_smem>>>();                                   // launch 3 (ncu slot)
  k_solve<<<1, 1024, solve_smem>>>((float*)d_out, s2e, s2b, n);          // launch 4
}